// round 13
// baseline (speedup 1.0000x reference)
#include <cuda_runtime.h>
#include <cuda_bf16.h>
#include <cstdint>

// -------------------- problem constants --------------------
#define NB 32
#define TT 2048
#define HS 1024
#define WROW 2048
#define NROWS (NB*TT)      // 65536

// -------------------- GEMM tiling --------------------------
#define CM 128             // CTA rows
#define CN 256             // CTA cols (a)
#define CK 32              // K chunk (bf16 elems) = 64B rows
#define KCH (HS/CK)        // 32 chunks
#define NSLICE (HS/CN)     // 4 partial score slices

// SMEM geometry: 64B rows + 16B pad = 80B stride (conflict-free for ldsm)
#define ROWB 80
#define TILE_A (CM*ROWB)   // 10240 B
#define TILE_B (CN*ROWB)   // 20480 B
#define BUFSZ (2*TILE_A + 2*TILE_B)  // 61440 B per stage
#define NSTAGE 3
#define SM_TOT (NSTAGE*BUFSZ)        // 184320 B -> 1 CTA/SM (256 thr)

#define CTX_SPLIT 16
#define CTX_TCH (TT/CTX_SPLIT)  // 128

// -------------------- device scratch (static, zero-initialized) ----
__device__ __nv_bfloat16 g_Ahi[(size_t)NROWS * HS];   // 128 MB
__device__ __nv_bfloat16 g_Alo[(size_t)NROWS * HS];   // 128 MB
__device__ __nv_bfloat16 g_Bhi[(size_t)HS * HS];      // We hi (2 MB)
__device__ __nv_bfloat16 g_Blo[(size_t)HS * HS];      // We lo
__device__ float g_decb[NB * HS];
__device__ float g_part[(size_t)NSLICE * NROWS];      // 1 MB
__device__ float g_ctxp[CTX_SPLIT * NB * HS];         // 2 MB

// -------------------- small helpers -------------------------
__device__ __forceinline__ uint32_t smem_u32(const void* p) {
    uint32_t a;
    asm("{ .reg .u64 t; cvta.to.shared.u64 t, %1; cvt.u32.u64 %0, t; }"
        : "=r"(a) : "l"(p));
    return a;
}

__device__ __forceinline__ void cp16(uint32_t dst, const void* src) {
    asm volatile("cp.async.cg.shared.global [%0], [%1], 16;"
                 :: "r"(dst), "l"(src));
}
__device__ __forceinline__ void cp_commit() {
    asm volatile("cp.async.commit_group;");
}
template <int N>
__device__ __forceinline__ void cp_wait() {
    asm volatile("cp.async.wait_group %0;" :: "n"(N));
}

__device__ __forceinline__ void ldsm4(uint32_t& r0, uint32_t& r1,
                                      uint32_t& r2, uint32_t& r3, uint32_t a) {
    asm volatile("ldmatrix.sync.aligned.m8n8.x4.shared.b16 {%0,%1,%2,%3}, [%4];"
                 : "=r"(r0), "=r"(r1), "=r"(r2), "=r"(r3) : "r"(a));
}

__device__ __forceinline__ void mma_bf16(float* c, const uint32_t* a,
                                         const uint32_t* b) {
    asm volatile(
        "mma.sync.aligned.m16n8k16.row.col.f32.bf16.bf16.f32 "
        "{%0,%1,%2,%3}, {%4,%5,%6,%7}, {%8,%9}, {%0,%1,%2,%3};"
        : "+f"(c[0]), "+f"(c[1]), "+f"(c[2]), "+f"(c[3])
        : "r"(a[0]), "r"(a[1]), "r"(a[2]), "r"(a[3]), "r"(b[0]), "r"(b[1]));
}

__device__ __forceinline__ float fast_tanh(float x) {
    float e = __expf(2.0f * x);
    return 1.0f - __fdividef(2.0f, e + 1.0f);
}

__device__ __forceinline__ void split_bf16(float x, unsigned short& h, unsigned short& l) {
    __nv_bfloat16 bh = __float2bfloat16(x);
    float r = x - __bfloat162float(bh);
    __nv_bfloat16 bl = __float2bfloat16(r);
    h = __bfloat16_as_ushort(bh);
    l = __bfloat16_as_ushort(bl);
}

// -------------------- conversion kernels --------------------
// grid (16, 32): x = t-block of 128 rows, y = n. Skips fully-masked blocks.
__global__ void convA_kernel(const float* __restrict__ x,
                             const int* __restrict__ src_lens) {
    const int n = blockIdx.y;
    const int tb = blockIdx.x;
    if (tb * 128 >= src_lens[n]) return;     // fully masked: skip (zeros stay)
    const size_t base = ((size_t)n * TT + (size_t)tb * 128) * HS;
    const int tid = threadIdx.x;
    #pragma unroll 4
    for (int it = 0; it < 128; it++) {
        size_t i = base + ((size_t)it * 256 + tid) * 4;
        float4 v = *reinterpret_cast<const float4*>(x + i);
        unsigned short h0, h1, h2, h3, l0, l1, l2, l3;
        split_bf16(v.x, h0, l0); split_bf16(v.y, h1, l1);
        split_bf16(v.z, h2, l2); split_bf16(v.w, h3, l3);
        uint2 hp, lp;
        hp.x = (uint32_t)h0 | ((uint32_t)h1 << 16);
        hp.y = (uint32_t)h2 | ((uint32_t)h3 << 16);
        lp.x = (uint32_t)l0 | ((uint32_t)l1 << 16);
        lp.y = (uint32_t)l2 | ((uint32_t)l3 << 16);
        *reinterpret_cast<uint2*>(&g_Ahi[i]) = hp;
        *reinterpret_cast<uint2*>(&g_Alo[i]) = lp;
    }
}

__global__ void convW_kernel(const float* __restrict__ W) {
    int a = blockIdx.x;
    int e4 = threadIdx.x * 4;
    float4 v = *reinterpret_cast<const float4*>(W + (size_t)a * WROW + HS + e4);
    unsigned short h0, h1, h2, h3, l0, l1, l2, l3;
    split_bf16(v.x, h0, l0); split_bf16(v.y, h1, l1);
    split_bf16(v.z, h2, l2); split_bf16(v.w, h3, l3);
    uint2 hp, lp;
    hp.x = (uint32_t)h0 | ((uint32_t)h1 << 16);
    hp.y = (uint32_t)h2 | ((uint32_t)h3 << 16);
    lp.x = (uint32_t)l0 | ((uint32_t)l1 << 16);
    lp.y = (uint32_t)l2 | ((uint32_t)l3 << 16);
    size_t o = (size_t)a * HS + e4;
    *reinterpret_cast<uint2*>(&g_Bhi[o]) = hp;
    *reinterpret_cast<uint2*>(&g_Blo[o]) = lp;
}

// -------------------- dec_proj + b (W rows loaded ONCE, loop over n) ----
// grid 128 blocks, 256 thr (8 warps). Warp w owns a = blk*8 + w.
__global__ void decproj_kernel(const float* __restrict__ h_dec,
                               const float* __restrict__ W,
                               const float* __restrict__ b) {
    const int warp = threadIdx.x >> 5;
    const int lane = threadIdx.x & 31;
    const int a = blockIdx.x * 8 + warp;
    const float* wrow = W + (size_t)a * WROW;   // Wd = first HS cols

    float wreg[32];
    #pragma unroll
    for (int i = 0; i < 32; i++) wreg[i] = wrow[lane + i * 32];
    const float bias = b[a];

    #pragma unroll 1
    for (int n = 0; n < NB; n++) {
        const float* hd = h_dec + n * HS;
        float s = 0.f;
        #pragma unroll
        for (int i = 0; i < 32; i++) s += hd[lane + i * 32] * wreg[i];
        #pragma unroll
        for (int off = 16; off > 0; off >>= 1)
            s += __shfl_xor_sync(0xffffffffu, s, off);
        if (lane == 0) g_decb[n * HS + a] = s + bias;
    }
}

// -------------------- main GEMM + score kernel --------------------
// grid (NSLICE=4, NROWS/CM=512)  block 256 (8 warps, 2m x 4n, 64x64 tiles)
// Skips blocks whose 128 rows are all masked (t0 >= src_len[n]).
__global__ void __launch_bounds__(256, 1)
gemm_score_kernel(const float* __restrict__ v,
                  const int* __restrict__ src_lens) {
    extern __shared__ char smem[];
    const uint32_t sb = smem_u32(smem);

    const int tid = threadIdx.x;
    const int lane = tid & 31;
    const int wid = tid >> 5;
    const int warp_m = wid & 1;        // 0..1 (64-row slices of 128)
    const int warp_n = wid >> 1;       // 0..3 (64-col slices of 256)

    const int bn = blockIdx.x;         // col block 0..3
    const int rb = blockIdx.y;         // row block 0..511
    const size_t gr0 = (size_t)rb * CM;
    const int a0 = bn * CN;
    const int n = rb >> 4;             // 16 row blocks per batch
    const int t0 = (rb & 15) * CM;     // first timestep of this block

    if (t0 >= src_lens[n]) return;     // all rows masked -> weight 0 anyway

    // ---- global load mapping (256 threads) ----
    const int ld_row = tid >> 2;       // 0..63
    const int ld_u = tid & 3;          // 16B unit
    const size_t srcA0 = (gr0 + ld_row) * (size_t)HS + ld_u * 8;
    const size_t srcA1 = (gr0 + 64 + ld_row) * (size_t)HS + ld_u * 8;
    const uint32_t dstA0 = ld_row * ROWB + ld_u * 16;
    const uint32_t dstA1 = (64 + ld_row) * ROWB + ld_u * 16;
    const size_t srcB = ((size_t)(a0 + ld_row)) * HS + ld_u * 8;
    const uint32_t dstB = ld_row * ROWB + ld_u * 16;

    float acc[4][8][4];
    #pragma unroll
    for (int i = 0; i < 4; i++)
        #pragma unroll
        for (int j = 0; j < 8; j++)
            #pragma unroll
            for (int r = 0; r < 4; r++) acc[i][j][r] = 0.f;

    // ---- ldmatrix per-thread address offsets ----
    const int m_sel = lane >> 3;
    const int m_off = ((m_sel & 1) << 3) + (lane & 7);
    const uint32_t a_kb = (m_sel >> 1) * 16;
    const uint32_t a_row0 = (warp_m * 64 + m_off) * ROWB + a_kb;
    const uint32_t b_pair0 =
        (warp_n * 64 + (lane & 7) + ((lane >> 4) << 3)) * ROWB
        + ((lane >> 3) & 1) * 16;

    #define ST_AHI 0
    #define ST_ALO TILE_A
    #define ST_BHI (2*TILE_A)
    #define ST_BLO (2*TILE_A + TILE_B)

    #define ISSUE_CHUNK(stbase, k0) do {                                     \
        const uint32_t _st = (stbase);                                       \
        const int _k0 = (k0);                                                \
        cp16(_st + ST_AHI + dstA0, g_Ahi + srcA0 + _k0);                     \
        cp16(_st + ST_AHI + dstA1, g_Ahi + srcA1 + _k0);                     \
        cp16(_st + ST_ALO + dstA0, g_Alo + srcA0 + _k0);                     \
        cp16(_st + ST_ALO + dstA1, g_Alo + srcA1 + _k0);                     \
        _Pragma("unroll")                                                    \
        for (int _l = 0; _l < 4; _l++) {                                     \
            cp16(_st + ST_BHI + dstB + _l * (64 * ROWB),                     \
                 g_Bhi + srcB + (size_t)_l * 64 * HS + _k0);                 \
            cp16(_st + ST_BLO + dstB + _l * (64 * ROWB),                     \
                 g_Blo + srcB + (size_t)_l * 64 * HS + _k0);                 \
        }                                                                    \
        cp_commit();                                                         \
    } while (0)

    // ---- prologue: issue chunks 0,1 ----
    ISSUE_CHUNK(sb + 0 * BUFSZ, 0 * CK);
    ISSUE_CHUNK(sb + 1 * BUFSZ, 1 * CK);

    int stg = 0;
    #pragma unroll 1
    for (int kk = 0; kk < KCH; kk++) {
        if (kk == KCH - 1) cp_wait<0>(); else cp_wait<1>();
        __syncthreads();

        // issue chunk kk+2 into stage (stg+2)%3 (the kk-1 buffer, drained)
        if (kk + 2 < KCH) {
            ISSUE_CHUNK(sb + ((stg + 2) % NSTAGE) * BUFSZ, (kk + 2) * CK);
        }

        const uint32_t bufb = sb + stg * BUFSZ;
        const uint32_t Ahi = bufb + ST_AHI;
        const uint32_t Alo = bufb + ST_ALO;
        const uint32_t Bhi = bufb + ST_BHI;
        const uint32_t Blo = bufb + ST_BLO;

        #pragma unroll
        for (int s = 0; s < 2; s++) {
            const uint32_t ks = s * 32;    // 16 k-elems per step
            uint32_t ah[4][4], al[4][4];
            #pragma unroll
            for (int i = 0; i < 4; i++) {
                uint32_t ra = a_row0 + i * 16 * ROWB + ks;
                ldsm4(ah[i][0], ah[i][1], ah[i][2], ah[i][3], Ahi + ra);
                ldsm4(al[i][0], al[i][1], al[i][2], al[i][3], Alo + ra);
            }
            uint32_t bb[4][4];
            #pragma unroll
            for (int jp = 0; jp < 4; jp++) {
                uint32_t rbo = b_pair0 + jp * 16 * ROWB + ks;
                ldsm4(bb[jp][0], bb[jp][1], bb[jp][2], bb[jp][3], Bhi + rbo);
            }
            // pass 1: Ahi * Bhi
            #pragma unroll
            for (int jp = 0; jp < 4; jp++)
                #pragma unroll
                for (int i = 0; i < 4; i++) {
                    mma_bf16(acc[i][2 * jp],     ah[i], &bb[jp][0]);
                    mma_bf16(acc[i][2 * jp + 1], ah[i], &bb[jp][2]);
                }
            // pass 2: Alo * Bhi
            #pragma unroll
            for (int jp = 0; jp < 4; jp++)
                #pragma unroll
                for (int i = 0; i < 4; i++) {
                    mma_bf16(acc[i][2 * jp],     al[i], &bb[jp][0]);
                    mma_bf16(acc[i][2 * jp + 1], al[i], &bb[jp][2]);
                }
            // reload B registers with Blo
            #pragma unroll
            for (int jp = 0; jp < 4; jp++) {
                uint32_t rbo = b_pair0 + jp * 16 * ROWB + ks;
                ldsm4(bb[jp][0], bb[jp][1], bb[jp][2], bb[jp][3], Blo + rbo);
            }
            // pass 3: Ahi * Blo
            #pragma unroll
            for (int jp = 0; jp < 4; jp++)
                #pragma unroll
                for (int i = 0; i < 4; i++) {
                    mma_bf16(acc[i][2 * jp],     ah[i], &bb[jp][0]);
                    mma_bf16(acc[i][2 * jp + 1], ah[i], &bb[jp][2]);
                }
        }
        stg = (stg + 1) % NSTAGE;
    }

    // -------------------- epilogue: tanh + v-dot --------------------
    float pr[8];
    #pragma unroll
    for (int q = 0; q < 8; q++) pr[q] = 0.f;
    #pragma unroll
    for (int j = 0; j < 8; j++) {
        int col = a0 + warp_n * 64 + j * 8 + (lane & 3) * 2;
        float2 v2 = *reinterpret_cast<const float2*>(v + col);
        float2 d2 = *reinterpret_cast<const float2*>(g_decb + n * HS + col);
        #pragma unroll
        for (int i = 0; i < 4; i++) {
            pr[i * 2 + 0] += v2.x * fast_tanh(acc[i][j][0] + d2.x)
                           + v2.y * fast_tanh(acc[i][j][1] + d2.y);
            pr[i * 2 + 1] += v2.x * fast_tanh(acc[i][j][2] + d2.x)
                           + v2.y * fast_tanh(acc[i][j][3] + d2.y);
        }
    }
    #pragma unroll
    for (int q = 0; q < 8; q++) {
        pr[q] += __shfl_xor_sync(0xffffffffu, pr[q], 1);
        pr[q] += __shfl_xor_sync(0xffffffffu, pr[q], 2);
    }
    float* red = reinterpret_cast<float*>(smem);   // reuse: [128][4]
    __syncthreads();
    if ((lane & 3) == 0) {
        #pragma unroll
        for (int q = 0; q < 8; q++) {
            int row = warp_m * 64 + (q >> 1) * 16 + (lane >> 2) + (q & 1) * 8;
            red[row * 4 + warp_n] = pr[q];
        }
    }
    __syncthreads();
    if (tid < 128) {
        float s = red[tid * 4 + 0] + red[tid * 4 + 1]
                + red[tid * 4 + 2] + red[tid * 4 + 3];
        g_part[(size_t)bn * NROWS + gr0 + tid] = s;
    }
}

// -------------------- masked softmax (512 threads) --------------------
__global__ void softmax_kernel(const int* __restrict__ src_lens,
                               float* __restrict__ weights_out) {
    const int n = blockIdx.x;
    const int tid = threadIdx.x;
    const int len = src_lens[n];
    __shared__ float red[512];

    float sc[4];
    float mx = -1e30f;
    #pragma unroll
    for (int i = 0; i < 4; i++) {
        int t = i * 512 + tid;
        float s = 0.f;
        #pragma unroll
        for (int p = 0; p < NSLICE; p++)
            s += g_part[(size_t)p * NROWS + (size_t)n * TT + t];
        s = (t < len) ? s : -1e10f;
        sc[i] = s;
        mx = fmaxf(mx, s);
    }
    red[tid] = mx; __syncthreads();
    for (int s = 256; s > 0; s >>= 1) {
        if (tid < s) red[tid] = fmaxf(red[tid], red[tid + s]);
        __syncthreads();
    }
    mx = red[0]; __syncthreads();

    float sum = 0.f;
    #pragma unroll
    for (int i = 0; i < 4; i++) { sc[i] = __expf(sc[i] - mx); sum += sc[i]; }
    red[tid] = sum; __syncthreads();
    for (int s = 256; s > 0; s >>= 1) {
        if (tid < s) red[tid] += red[tid + s];
        __syncthreads();
    }
    float inv = __fdividef(1.0f, red[0]);
    #pragma unroll
    for (int i = 0; i < 4; i++) {
        int t = i * 512 + tid;
        weights_out[(size_t)n * TT + t] = sc[i] * inv;
    }
}

// -------------------- ctx (16-way T split + reduce) --------------------
__global__ void ctx_part_kernel(const float* __restrict__ h_enc,
                                const float* __restrict__ weights,
                                const int* __restrict__ src_lens) {
    const int n = blockIdx.x;
    const int ts = blockIdx.z;
    const int t0 = ts * CTX_TCH;
    if (t0 >= src_lens[n]) return;   // weights exactly 0 there; slot stays 0
    const int e = blockIdx.y * 256 + threadIdx.x;
    const float* base = h_enc + ((size_t)n * TT + t0) * HS + e;
    const float* wrow = weights + (size_t)n * TT + t0;
    float acc = 0.f;
    #pragma unroll 8
    for (int t = 0; t < CTX_TCH; t++)
        acc = fmaf(wrow[t], base[(size_t)t * HS], acc);
    g_ctxp[((size_t)ts * NB + n) * HS + e] = acc;
}

__global__ void ctx_reduce_kernel(float* __restrict__ ctx_out) {
    int i = blockIdx.x * 256 + threadIdx.x;
    float s = 0.f;
    #pragma unroll
    for (int ts = 0; ts < CTX_SPLIT; ts++)
        s += g_ctxp[(size_t)ts * (NB * HS) + i];
    ctx_out[i] = s;
}

// -------------------- launch --------------------
extern "C" void kernel_launch(void* const* d_in, const int* in_sizes, int n_in,
                              void* d_out, int out_size) {
    const float* h_dec    = (const float*)d_in[0];
    const float* h_enc    = (const float*)d_in[1];
    const int*   src_lens = (const int*)  d_in[2];
    const float* W        = (const float*)d_in[3];
    const float* b        = (const float*)d_in[4];
    const float* v        = (const float*)d_in[5];

    float* ctx_out     = (float*)d_out;
    float* weights_out = (float*)d_out + NB * HS;

    static int smem_set = 0;
    if (!smem_set) {
        cudaFuncSetAttribute(gemm_score_kernel,
                             cudaFuncAttributeMaxDynamicSharedMemorySize, SM_TOT);
        smem_set = 1;
    }

    convA_kernel<<<dim3(16, NB), 256>>>(h_enc, src_lens);
    convW_kernel<<<1024, 256>>>(W);
    decproj_kernel<<<128, 256>>>(h_dec, W, b);
    gemm_score_kernel<<<dim3(NSLICE, NROWS / CM), 256, SM_TOT>>>(v, src_lens);
    softmax_kernel<<<NB, 512>>>(src_lens, weights_out);
    ctx_part_kernel<<<dim3(NB, HS / 256, CTX_SPLIT), 256>>>(h_enc, weights_out, src_lens);
    ctx_reduce_kernel<<<128, 256>>>(ctx_out);
}

// round 14
// speedup vs baseline: 1.1506x; 1.1506x over previous
#include <cuda_runtime.h>
#include <cuda_bf16.h>
#include <cstdint>

// -------------------- problem constants --------------------
#define NB 32
#define TT 2048
#define HS 1024
#define WROW 2048
#define NROWS (NB*TT)      // 65536

// -------------------- GEMM tiling --------------------------
#define CM 128             // CTA rows
#define CN 256             // CTA cols (a)
#define CK 32              // K chunk (bf16 elems) = 64B rows
#define KCH (HS/CK)        // 32 chunks
#define NSLICE (HS/CN)     // 4 partial score slices

// SMEM geometry: 64B rows + 16B pad = 80B stride (conflict-free for ldsm)
#define ROWB 80
#define TILE_A (CM*ROWB)   // 10240 B
#define TILE_B (CN*ROWB)   // 20480 B
#define BUFSZ (2*TILE_A + 2*TILE_B)  // 61440 B per stage
#define NSTAGE 3
#define SM_TOT (NSTAGE*BUFSZ)        // 184320 B -> 1 CTA/SM (256 thr)

#define CTX_SPLIT 16
#define CTX_TCH (TT/CTX_SPLIT)  // 128

// -------------------- device scratch (static, zero-initialized) ----
__device__ __nv_bfloat16 g_Ahi[(size_t)NROWS * HS];   // 128 MB
__device__ __nv_bfloat16 g_Alo[(size_t)NROWS * HS];   // 128 MB
__device__ __nv_bfloat16 g_Bhi[(size_t)HS * HS];      // We hi (2 MB)
__device__ __nv_bfloat16 g_Blo[(size_t)HS * HS];      // We lo
__device__ float g_decb[NB * HS];
__device__ float g_part[(size_t)NSLICE * NROWS];      // 1 MB
__device__ float g_ctxp[CTX_SPLIT * NB * HS];         // 2 MB

// -------------------- small helpers -------------------------
__device__ __forceinline__ uint32_t smem_u32(const void* p) {
    uint32_t a;
    asm("{ .reg .u64 t; cvta.to.shared.u64 t, %1; cvt.u32.u64 %0, t; }"
        : "=r"(a) : "l"(p));
    return a;
}

__device__ __forceinline__ void cp16(uint32_t dst, const void* src) {
    asm volatile("cp.async.cg.shared.global [%0], [%1], 16;"
                 :: "r"(dst), "l"(src));
}
__device__ __forceinline__ void cp_commit() {
    asm volatile("cp.async.commit_group;");
}
template <int N>
__device__ __forceinline__ void cp_wait() {
    asm volatile("cp.async.wait_group %0;" :: "n"(N));
}

__device__ __forceinline__ void ldsm4(uint32_t& r0, uint32_t& r1,
                                      uint32_t& r2, uint32_t& r3, uint32_t a) {
    asm volatile("ldmatrix.sync.aligned.m8n8.x4.shared.b16 {%0,%1,%2,%3}, [%4];"
                 : "=r"(r0), "=r"(r1), "=r"(r2), "=r"(r3) : "r"(a));
}

__device__ __forceinline__ void mma_bf16(float* c, const uint32_t* a,
                                         const uint32_t* b) {
    asm volatile(
        "mma.sync.aligned.m16n8k16.row.col.f32.bf16.bf16.f32 "
        "{%0,%1,%2,%3}, {%4,%5,%6,%7}, {%8,%9}, {%0,%1,%2,%3};"
        : "+f"(c[0]), "+f"(c[1]), "+f"(c[2]), "+f"(c[3])
        : "r"(a[0]), "r"(a[1]), "r"(a[2]), "r"(a[3]), "r"(b[0]), "r"(b[1]));
}

__device__ __forceinline__ float fast_tanh(float x) {
    float e = __expf(2.0f * x);
    return 1.0f - __fdividef(2.0f, e + 1.0f);
}

__device__ __forceinline__ void split_bf16(float x, unsigned short& h, unsigned short& l) {
    __nv_bfloat16 bh = __float2bfloat16(x);
    float r = x - __bfloat162float(bh);
    __nv_bfloat16 bl = __float2bfloat16(r);
    h = __bfloat16_as_ushort(bh);
    l = __bfloat16_as_ushort(bl);
}

// -------------------- conversion kernels --------------------
// grid (32, 32): x = t-block of 64 rows, y = n. Skips fully-masked blocks.
__global__ void convA_kernel(const float* __restrict__ x,
                             const int* __restrict__ src_lens) {
    const int n = blockIdx.y;
    const int tb = blockIdx.x;
    if (tb * 64 >= src_lens[n]) return;      // fully masked: skip (zeros stay)
    const size_t base = ((size_t)n * TT + (size_t)tb * 64) * HS;
    const int tid = threadIdx.x;
    #pragma unroll 4
    for (int it = 0; it < 64; it++) {
        size_t i = base + ((size_t)it * 256 + tid) * 4;
        float4 v = *reinterpret_cast<const float4*>(x + i);
        unsigned short h0, h1, h2, h3, l0, l1, l2, l3;
        split_bf16(v.x, h0, l0); split_bf16(v.y, h1, l1);
        split_bf16(v.z, h2, l2); split_bf16(v.w, h3, l3);
        uint2 hp, lp;
        hp.x = (uint32_t)h0 | ((uint32_t)h1 << 16);
        hp.y = (uint32_t)h2 | ((uint32_t)h3 << 16);
        lp.x = (uint32_t)l0 | ((uint32_t)l1 << 16);
        lp.y = (uint32_t)l2 | ((uint32_t)l3 << 16);
        *reinterpret_cast<uint2*>(&g_Ahi[i]) = hp;
        *reinterpret_cast<uint2*>(&g_Alo[i]) = lp;
    }
}

__global__ void convW_kernel(const float* __restrict__ W) {
    int a = blockIdx.x;
    int e4 = threadIdx.x * 4;
    float4 v = *reinterpret_cast<const float4*>(W + (size_t)a * WROW + HS + e4);
    unsigned short h0, h1, h2, h3, l0, l1, l2, l3;
    split_bf16(v.x, h0, l0); split_bf16(v.y, h1, l1);
    split_bf16(v.z, h2, l2); split_bf16(v.w, h3, l3);
    uint2 hp, lp;
    hp.x = (uint32_t)h0 | ((uint32_t)h1 << 16);
    hp.y = (uint32_t)h2 | ((uint32_t)h3 << 16);
    lp.x = (uint32_t)l0 | ((uint32_t)l1 << 16);
    lp.y = (uint32_t)l2 | ((uint32_t)l3 << 16);
    size_t o = (size_t)a * HS + e4;
    *reinterpret_cast<uint2*>(&g_Bhi[o]) = hp;
    *reinterpret_cast<uint2*>(&g_Blo[o]) = lp;
}

// -------------------- dec_proj + b (R11 form) --------------------
__global__ void decproj_kernel(const float* __restrict__ h_dec,
                               const float* __restrict__ W,
                               const float* __restrict__ b) {
    int warp = threadIdx.x >> 5;
    int lane = threadIdx.x & 31;
    int a = blockIdx.x * 8 + warp;
    int n = blockIdx.y;
    const float* wrow = W + (size_t)a * WROW;
    const float* hd = h_dec + n * HS;
    float s = 0.f;
    #pragma unroll 8
    for (int d = lane; d < HS; d += 32) s += hd[d] * wrow[d];
    #pragma unroll
    for (int off = 16; off > 0; off >>= 1) s += __shfl_xor_sync(0xffffffffu, s, off);
    if (lane == 0) g_decb[n * HS + a] = s + b[a];
}

// -------------------- main GEMM + score kernel (R11, unchanged) --------
__global__ void __launch_bounds__(256, 1)
gemm_score_kernel(const float* __restrict__ v,
                  const int* __restrict__ src_lens) {
    extern __shared__ char smem[];
    const uint32_t sb = smem_u32(smem);

    const int tid = threadIdx.x;
    const int lane = tid & 31;
    const int wid = tid >> 5;
    const int warp_m = wid & 1;        // 0..1 (64-row slices of 128)
    const int warp_n = wid >> 1;       // 0..3 (64-col slices of 256)

    const int bn = blockIdx.x;         // col block 0..3
    const int rb = blockIdx.y;         // row block 0..511
    const size_t gr0 = (size_t)rb * CM;
    const int a0 = bn * CN;
    const int n = rb >> 4;             // 16 row blocks per batch
    const int t0 = (rb & 15) * CM;     // first timestep of this block

    if (t0 >= src_lens[n]) return;     // all rows masked -> weight 0 anyway

    // ---- global load mapping (256 threads) ----
    const int ld_row = tid >> 2;       // 0..63
    const int ld_u = tid & 3;          // 16B unit
    const size_t srcA0 = (gr0 + ld_row) * (size_t)HS + ld_u * 8;
    const size_t srcA1 = (gr0 + 64 + ld_row) * (size_t)HS + ld_u * 8;
    const uint32_t dstA0 = ld_row * ROWB + ld_u * 16;
    const uint32_t dstA1 = (64 + ld_row) * ROWB + ld_u * 16;
    const size_t srcB = ((size_t)(a0 + ld_row)) * HS + ld_u * 8;
    const uint32_t dstB = ld_row * ROWB + ld_u * 16;

    float acc[4][8][4];
    #pragma unroll
    for (int i = 0; i < 4; i++)
        #pragma unroll
        for (int j = 0; j < 8; j++)
            #pragma unroll
            for (int r = 0; r < 4; r++) acc[i][j][r] = 0.f;

    // ---- ldmatrix per-thread address offsets ----
    const int m_sel = lane >> 3;
    const int m_off = ((m_sel & 1) << 3) + (lane & 7);
    const uint32_t a_kb = (m_sel >> 1) * 16;
    const uint32_t a_row0 = (warp_m * 64 + m_off) * ROWB + a_kb;
    const uint32_t b_pair0 =
        (warp_n * 64 + (lane & 7) + ((lane >> 4) << 3)) * ROWB
        + ((lane >> 3) & 1) * 16;

    #define ST_AHI 0
    #define ST_ALO TILE_A
    #define ST_BHI (2*TILE_A)
    #define ST_BLO (2*TILE_A + TILE_B)

    #define ISSUE_CHUNK(stbase, k0) do {                                     \
        const uint32_t _st = (stbase);                                       \
        const int _k0 = (k0);                                                \
        cp16(_st + ST_AHI + dstA0, g_Ahi + srcA0 + _k0);                     \
        cp16(_st + ST_AHI + dstA1, g_Ahi + srcA1 + _k0);                     \
        cp16(_st + ST_ALO + dstA0, g_Alo + srcA0 + _k0);                     \
        cp16(_st + ST_ALO + dstA1, g_Alo + srcA1 + _k0);                     \
        _Pragma("unroll")                                                    \
        for (int _l = 0; _l < 4; _l++) {                                     \
            cp16(_st + ST_BHI + dstB + _l * (64 * ROWB),                     \
                 g_Bhi + srcB + (size_t)_l * 64 * HS + _k0);                 \
            cp16(_st + ST_BLO + dstB + _l * (64 * ROWB),                     \
                 g_Blo + srcB + (size_t)_l * 64 * HS + _k0);                 \
        }                                                                    \
        cp_commit();                                                         \
    } while (0)

    // ---- prologue: issue chunks 0,1 ----
    ISSUE_CHUNK(sb + 0 * BUFSZ, 0 * CK);
    ISSUE_CHUNK(sb + 1 * BUFSZ, 1 * CK);

    int stg = 0;
    #pragma unroll 1
    for (int kk = 0; kk < KCH; kk++) {
        if (kk == KCH - 1) cp_wait<0>(); else cp_wait<1>();
        __syncthreads();

        // issue chunk kk+2 into stage (stg+2)%3 (the kk-1 buffer, drained)
        if (kk + 2 < KCH) {
            ISSUE_CHUNK(sb + ((stg + 2) % NSTAGE) * BUFSZ, (kk + 2) * CK);
        }

        const uint32_t bufb = sb + stg * BUFSZ;
        const uint32_t Ahi = bufb + ST_AHI;
        const uint32_t Alo = bufb + ST_ALO;
        const uint32_t Bhi = bufb + ST_BHI;
        const uint32_t Blo = bufb + ST_BLO;

        #pragma unroll
        for (int s = 0; s < 2; s++) {
            const uint32_t ks = s * 32;    // 16 k-elems per step
            uint32_t ah[4][4], al[4][4];
            #pragma unroll
            for (int i = 0; i < 4; i++) {
                uint32_t ra = a_row0 + i * 16 * ROWB + ks;
                ldsm4(ah[i][0], ah[i][1], ah[i][2], ah[i][3], Ahi + ra);
                ldsm4(al[i][0], al[i][1], al[i][2], al[i][3], Alo + ra);
            }
            uint32_t bb[4][4];
            #pragma unroll
            for (int jp = 0; jp < 4; jp++) {
                uint32_t rbo = b_pair0 + jp * 16 * ROWB + ks;
                ldsm4(bb[jp][0], bb[jp][1], bb[jp][2], bb[jp][3], Bhi + rbo);
            }
            // pass 1: Ahi * Bhi
            #pragma unroll
            for (int jp = 0; jp < 4; jp++)
                #pragma unroll
                for (int i = 0; i < 4; i++) {
                    mma_bf16(acc[i][2 * jp],     ah[i], &bb[jp][0]);
                    mma_bf16(acc[i][2 * jp + 1], ah[i], &bb[jp][2]);
                }
            // pass 2: Alo * Bhi
            #pragma unroll
            for (int jp = 0; jp < 4; jp++)
                #pragma unroll
                for (int i = 0; i < 4; i++) {
                    mma_bf16(acc[i][2 * jp],     al[i], &bb[jp][0]);
                    mma_bf16(acc[i][2 * jp + 1], al[i], &bb[jp][2]);
                }
            // reload B registers with Blo
            #pragma unroll
            for (int jp = 0; jp < 4; jp++) {
                uint32_t rbo = b_pair0 + jp * 16 * ROWB + ks;
                ldsm4(bb[jp][0], bb[jp][1], bb[jp][2], bb[jp][3], Blo + rbo);
            }
            // pass 3: Ahi * Blo
            #pragma unroll
            for (int jp = 0; jp < 4; jp++)
                #pragma unroll
                for (int i = 0; i < 4; i++) {
                    mma_bf16(acc[i][2 * jp],     ah[i], &bb[jp][0]);
                    mma_bf16(acc[i][2 * jp + 1], ah[i], &bb[jp][2]);
                }
        }
        stg = (stg + 1) % NSTAGE;
    }

    // -------------------- epilogue: tanh + v-dot --------------------
    float pr[8];
    #pragma unroll
    for (int q = 0; q < 8; q++) pr[q] = 0.f;
    #pragma unroll
    for (int j = 0; j < 8; j++) {
        int col = a0 + warp_n * 64 + j * 8 + (lane & 3) * 2;
        float2 v2 = *reinterpret_cast<const float2*>(v + col);
        float2 d2 = *reinterpret_cast<const float2*>(g_decb + n * HS + col);
        #pragma unroll
        for (int i = 0; i < 4; i++) {
            pr[i * 2 + 0] += v2.x * fast_tanh(acc[i][j][0] + d2.x)
                           + v2.y * fast_tanh(acc[i][j][1] + d2.y);
            pr[i * 2 + 1] += v2.x * fast_tanh(acc[i][j][2] + d2.x)
                           + v2.y * fast_tanh(acc[i][j][3] + d2.y);
        }
    }
    #pragma unroll
    for (int q = 0; q < 8; q++) {
        pr[q] += __shfl_xor_sync(0xffffffffu, pr[q], 1);
        pr[q] += __shfl_xor_sync(0xffffffffu, pr[q], 2);
    }
    float* red = reinterpret_cast<float*>(smem);   // reuse: [128][4]
    __syncthreads();
    if ((lane & 3) == 0) {
        #pragma unroll
        for (int q = 0; q < 8; q++) {
            int row = warp_m * 64 + (q >> 1) * 16 + (lane >> 2) + (q & 1) * 8;
            red[row * 4 + warp_n] = pr[q];
        }
    }
    __syncthreads();
    if (tid < 128) {
        float s = red[tid * 4 + 0] + red[tid * 4 + 1]
                + red[tid * 4 + 2] + red[tid * 4 + 3];
        g_part[(size_t)bn * NROWS + gr0 + tid] = s;
    }
}

// -------------------- masked softmax (R11 form) --------------------
__global__ void softmax_kernel(const int* __restrict__ src_lens,
                               float* __restrict__ weights_out) {
    const int n = blockIdx.x;
    const int tid = threadIdx.x;
    const int len = src_lens[n];
    __shared__ float red[256];

    float sc[8];
    float mx = -1e30f;
    #pragma unroll
    for (int i = 0; i < 8; i++) {
        int t = i * 256 + tid;
        float s = 0.f;
        #pragma unroll
        for (int p = 0; p < NSLICE; p++)
            s += g_part[(size_t)p * NROWS + (size_t)n * TT + t];
        s = (t < len) ? s : -1e10f;
        sc[i] = s;
        mx = fmaxf(mx, s);
    }
    red[tid] = mx; __syncthreads();
    for (int s = 128; s > 0; s >>= 1) {
        if (tid < s) red[tid] = fmaxf(red[tid], red[tid + s]);
        __syncthreads();
    }
    mx = red[0]; __syncthreads();

    float sum = 0.f;
    #pragma unroll
    for (int i = 0; i < 8; i++) { sc[i] = __expf(sc[i] - mx); sum += sc[i]; }
    red[tid] = sum; __syncthreads();
    for (int s = 128; s > 0; s >>= 1) {
        if (tid < s) red[tid] += red[tid + s];
        __syncthreads();
    }
    float inv = __fdividef(1.0f, red[0]);
    #pragma unroll
    for (int i = 0; i < 8; i++) {
        int t = i * 256 + tid;
        weights_out[(size_t)n * TT + t] = sc[i] * inv;
    }
}

// -------------------- ctx (16-way T split + reduce) --------------------
__global__ void ctx_part_kernel(const float* __restrict__ h_enc,
                                const float* __restrict__ weights,
                                const int* __restrict__ src_lens) {
    const int n = blockIdx.x;
    const int ts = blockIdx.z;
    const int t0 = ts * CTX_TCH;
    if (t0 >= src_lens[n]) return;   // weights exactly 0 there; slot stays 0
    const int e = blockIdx.y * 256 + threadIdx.x;
    const float* base = h_enc + ((size_t)n * TT + t0) * HS + e;
    const float* wrow = weights + (size_t)n * TT + t0;
    float acc = 0.f;
    #pragma unroll 8
    for (int t = 0; t < CTX_TCH; t++)
        acc = fmaf(wrow[t], base[(size_t)t * HS], acc);
    g_ctxp[((size_t)ts * NB + n) * HS + e] = acc;
}

__global__ void ctx_reduce_kernel(float* __restrict__ ctx_out) {
    int i = blockIdx.x * 256 + threadIdx.x;
    float s = 0.f;
    #pragma unroll
    for (int ts = 0; ts < CTX_SPLIT; ts++)
        s += g_ctxp[(size_t)ts * (NB * HS) + i];
    ctx_out[i] = s;
}

// -------------------- launch --------------------
extern "C" void kernel_launch(void* const* d_in, const int* in_sizes, int n_in,
                              void* d_out, int out_size) {
    const float* h_dec    = (const float*)d_in[0];
    const float* h_enc    = (const float*)d_in[1];
    const int*   src_lens = (const int*)  d_in[2];
    const float* W        = (const float*)d_in[3];
    const float* b        = (const float*)d_in[4];
    const float* v        = (const float*)d_in[5];

    float* ctx_out     = (float*)d_out;
    float* weights_out = (float*)d_out + NB * HS;

    // one-time setup (outside capture: first call is the correctness run)
    static cudaStream_t s2 = nullptr;
    static cudaEvent_t evFork = nullptr, evJoin = nullptr;
    if (!s2) {
        cudaFuncSetAttribute(gemm_score_kernel,
                             cudaFuncAttributeMaxDynamicSharedMemorySize, SM_TOT);
        cudaStreamCreateWithFlags(&s2, cudaStreamNonBlocking);
        cudaEventCreateWithFlags(&evFork, cudaEventDisableTiming);
        cudaEventCreateWithFlags(&evJoin, cudaEventDisableTiming);
    }

    // fork: convW + decproj on s2, convA on main stream (all independent)
    cudaEventRecord(evFork, 0);
    cudaStreamWaitEvent(s2, evFork, 0);
    convW_kernel<<<1024, 256, 0, s2>>>(W);
    decproj_kernel<<<dim3(HS / 8, NB), 256, 0, s2>>>(h_dec, W, b);
    cudaEventRecord(evJoin, s2);

    convA_kernel<<<dim3(32, NB), 256>>>(h_enc, src_lens);

    // join before gemm (needs g_Bhi/g_Blo/g_decb and g_Ahi/g_Alo)
    cudaStreamWaitEvent(0, evJoin, 0);

    gemm_score_kernel<<<dim3(NSLICE, NROWS / CM), 256, SM_TOT>>>(v, src_lens);
    softmax_kernel<<<NB, 256>>>(src_lens, weights_out);
    ctx_part_kernel<<<dim3(NB, HS / 256, CTX_SPLIT), 256>>>(h_enc, weights_out, src_lens);
    ctx_reduce_kernel<<<128, 256>>>(ctx_out);
}

// round 16
// speedup vs baseline: 1.1578x; 1.0063x over previous
#include <cuda_runtime.h>
#include <cuda_bf16.h>
#include <cstdint>

// -------------------- problem constants --------------------
#define NB 32
#define TT 2048
#define HS 1024
#define WROW 2048
#define NROWS (NB*TT)      // 65536

// -------------------- GEMM tiling --------------------------
#define CM 128             // CTA rows
#define CN 256             // CTA cols (a)
#define CK 32              // K chunk (bf16 elems) = 64B rows
#define KCH (HS/CK)        // 32 chunks
#define NSLICE (HS/CN)     // 4 partial score slices

// SMEM geometry: 64B rows + 16B pad = 80B stride (conflict-free for ldsm)
#define ROWB 80
#define TILE_A (CM*ROWB)   // 10240 B
#define TILE_B (CN*ROWB)   // 20480 B
#define BUFSZ (2*TILE_A + 2*TILE_B)  // 61440 B per stage
#define NSTAGE 3
#define SM_TOT (NSTAGE*BUFSZ)        // 184320 B -> 1 CTA/SM (256 thr)

#define CTX_SPLIT 32
#define CTX_TCH (TT/CTX_SPLIT)  // 64

// -------------------- device scratch (static, zero-initialized) ----
__device__ __nv_bfloat16 g_Ahi[(size_t)NROWS * HS];   // 128 MB
__device__ __nv_bfloat16 g_Alo[(size_t)NROWS * HS];   // 128 MB
__device__ __nv_bfloat16 g_Bhi[(size_t)HS * HS];      // We hi (2 MB)
__device__ __nv_bfloat16 g_Blo[(size_t)HS * HS];      // We lo
__device__ float g_decb[NB * HS];
__device__ float g_part[(size_t)NSLICE * NROWS];      // 1 MB
__device__ float g_ctxp[CTX_SPLIT * NB * HS];         // 4 MB

// -------------------- small helpers -------------------------
__device__ __forceinline__ uint32_t smem_u32(const void* p) {
    uint32_t a;
    asm("{ .reg .u64 t; cvta.to.shared.u64 t, %1; cvt.u32.u64 %0, t; }"
        : "=r"(a) : "l"(p));
    return a;
}

__device__ __forceinline__ void cp16(uint32_t dst, const void* src) {
    asm volatile("cp.async.cg.shared.global [%0], [%1], 16;"
                 :: "r"(dst), "l"(src));
}
__device__ __forceinline__ void cp_commit() {
    asm volatile("cp.async.commit_group;");
}
template <int N>
__device__ __forceinline__ void cp_wait() {
    asm volatile("cp.async.wait_group %0;" :: "n"(N));
}

__device__ __forceinline__ void ldsm4(uint32_t& r0, uint32_t& r1,
                                      uint32_t& r2, uint32_t& r3, uint32_t a) {
    asm volatile("ldmatrix.sync.aligned.m8n8.x4.shared.b16 {%0,%1,%2,%3}, [%4];"
                 : "=r"(r0), "=r"(r1), "=r"(r2), "=r"(r3) : "r"(a));
}

__device__ __forceinline__ void mma_bf16(float* c, const uint32_t* a,
                                         const uint32_t* b) {
    asm volatile(
        "mma.sync.aligned.m16n8k16.row.col.f32.bf16.bf16.f32 "
        "{%0,%1,%2,%3}, {%4,%5,%6,%7}, {%8,%9}, {%0,%1,%2,%3};"
        : "+f"(c[0]), "+f"(c[1]), "+f"(c[2]), "+f"(c[3])
        : "r"(a[0]), "r"(a[1]), "r"(a[2]), "r"(a[3]), "r"(b[0]), "r"(b[1]));
}

__device__ __forceinline__ float fast_tanh(float x) {
    float e = __expf(2.0f * x);
    return 1.0f - __fdividef(2.0f, e + 1.0f);
}

__device__ __forceinline__ void split_bf16(float x, unsigned short& h, unsigned short& l) {
    __nv_bfloat16 bh = __float2bfloat16(x);
    float r = x - __bfloat162float(bh);
    __nv_bfloat16 bl = __float2bfloat16(r);
    h = __bfloat16_as_ushort(bh);
    l = __bfloat16_as_ushort(bl);
}

// -------------------- conversion kernels --------------------
// grid (32, 32): x = t-block of 64 rows, y = n. Skips fully-masked blocks.
__global__ void convA_kernel(const float* __restrict__ x,
                             const int* __restrict__ src_lens) {
    const int n = blockIdx.y;
    const int tb = blockIdx.x;
    if (tb * 64 >= src_lens[n]) return;      // fully masked: skip (zeros stay)
    const size_t base = ((size_t)n * TT + (size_t)tb * 64) * HS;
    const int tid = threadIdx.x;
    #pragma unroll 4
    for (int it = 0; it < 64; it++) {
        size_t i = base + ((size_t)it * 256 + tid) * 4;
        float4 v = *reinterpret_cast<const float4*>(x + i);
        unsigned short h0, h1, h2, h3, l0, l1, l2, l3;
        split_bf16(v.x, h0, l0); split_bf16(v.y, h1, l1);
        split_bf16(v.z, h2, l2); split_bf16(v.w, h3, l3);
        uint2 hp, lp;
        hp.x = (uint32_t)h0 | ((uint32_t)h1 << 16);
        hp.y = (uint32_t)h2 | ((uint32_t)h3 << 16);
        lp.x = (uint32_t)l0 | ((uint32_t)l1 << 16);
        lp.y = (uint32_t)l2 | ((uint32_t)l3 << 16);
        *reinterpret_cast<uint2*>(&g_Ahi[i]) = hp;
        *reinterpret_cast<uint2*>(&g_Alo[i]) = lp;
    }
}

__global__ void convW_kernel(const float* __restrict__ W) {
    int a = blockIdx.x;
    int e4 = threadIdx.x * 4;
    float4 v = *reinterpret_cast<const float4*>(W + (size_t)a * WROW + HS + e4);
    unsigned short h0, h1, h2, h3, l0, l1, l2, l3;
    split_bf16(v.x, h0, l0); split_bf16(v.y, h1, l1);
    split_bf16(v.z, h2, l2); split_bf16(v.w, h3, l3);
    uint2 hp, lp;
    hp.x = (uint32_t)h0 | ((uint32_t)h1 << 16);
    hp.y = (uint32_t)h2 | ((uint32_t)h3 << 16);
    lp.x = (uint32_t)l0 | ((uint32_t)l1 << 16);
    lp.y = (uint32_t)l2 | ((uint32_t)l3 << 16);
    size_t o = (size_t)a * HS + e4;
    *reinterpret_cast<uint2*>(&g_Bhi[o]) = hp;
    *reinterpret_cast<uint2*>(&g_Blo[o]) = lp;
}

// -------------------- dec_proj + b --------------------
__global__ void decproj_kernel(const float* __restrict__ h_dec,
                               const float* __restrict__ W,
                               const float* __restrict__ b) {
    int warp = threadIdx.x >> 5;
    int lane = threadIdx.x & 31;
    int a = blockIdx.x * 8 + warp;
    int n = blockIdx.y;
    const float* wrow = W + (size_t)a * WROW;
    const float* hd = h_dec + n * HS;
    float s = 0.f;
    #pragma unroll 8
    for (int d = lane; d < HS; d += 32) s += hd[d] * wrow[d];
    #pragma unroll
    for (int off = 16; off > 0; off >>= 1) s += __shfl_xor_sync(0xffffffffu, s, off);
    if (lane == 0) g_decb[n * HS + a] = s + b[a];
}

// -------------------- main GEMM + score kernel (R11/R14, unchanged) ----
__global__ void __launch_bounds__(256, 1)
gemm_score_kernel(const float* __restrict__ v,
                  const int* __restrict__ src_lens) {
    extern __shared__ char smem[];
    const uint32_t sb = smem_u32(smem);

    const int tid = threadIdx.x;
    const int lane = tid & 31;
    const int wid = tid >> 5;
    const int warp_m = wid & 1;        // 0..1 (64-row slices of 128)
    const int warp_n = wid >> 1;       // 0..3 (64-col slices of 256)

    const int bn = blockIdx.x;         // col block 0..3
    const int rb = blockIdx.y;         // row block 0..511
    const size_t gr0 = (size_t)rb * CM;
    const int a0 = bn * CN;
    const int n = rb >> 4;             // 16 row blocks per batch
    const int t0 = (rb & 15) * CM;     // first timestep of this block

    if (t0 >= src_lens[n]) return;     // all rows masked -> weight 0 anyway

    // ---- global load mapping (256 threads) ----
    const int ld_row = tid >> 2;       // 0..63
    const int ld_u = tid & 3;          // 16B unit
    const size_t srcA0 = (gr0 + ld_row) * (size_t)HS + ld_u * 8;
    const size_t srcA1 = (gr0 + 64 + ld_row) * (size_t)HS + ld_u * 8;
    const uint32_t dstA0 = ld_row * ROWB + ld_u * 16;
    const uint32_t dstA1 = (64 + ld_row) * ROWB + ld_u * 16;
    const size_t srcB = ((size_t)(a0 + ld_row)) * HS + ld_u * 8;
    const uint32_t dstB = ld_row * ROWB + ld_u * 16;

    float acc[4][8][4];
    #pragma unroll
    for (int i = 0; i < 4; i++)
        #pragma unroll
        for (int j = 0; j < 8; j++)
            #pragma unroll
            for (int r = 0; r < 4; r++) acc[i][j][r] = 0.f;

    // ---- ldmatrix per-thread address offsets ----
    const int m_sel = lane >> 3;
    const int m_off = ((m_sel & 1) << 3) + (lane & 7);
    const uint32_t a_kb = (m_sel >> 1) * 16;
    const uint32_t a_row0 = (warp_m * 64 + m_off) * ROWB + a_kb;
    const uint32_t b_pair0 =
        (warp_n * 64 + (lane & 7) + ((lane >> 4) << 3)) * ROWB
        + ((lane >> 3) & 1) * 16;

    #define ST_AHI 0
    #define ST_ALO TILE_A
    #define ST_BHI (2*TILE_A)
    #define ST_BLO (2*TILE_A + TILE_B)

    #define ISSUE_CHUNK(stbase, k0) do {                                     \
        const uint32_t _st = (stbase);                                       \
        const int _k0 = (k0);                                                \
        cp16(_st + ST_AHI + dstA0, g_Ahi + srcA0 + _k0);                     \
        cp16(_st + ST_AHI + dstA1, g_Ahi + srcA1 + _k0);                     \
        cp16(_st + ST_ALO + dstA0, g_Alo + srcA0 + _k0);                     \
        cp16(_st + ST_ALO + dstA1, g_Alo + srcA1 + _k0);                     \
        _Pragma("unroll")                                                    \
        for (int _l = 0; _l < 4; _l++) {                                     \
            cp16(_st + ST_BHI + dstB + _l * (64 * ROWB),                     \
                 g_Bhi + srcB + (size_t)_l * 64 * HS + _k0);                 \
            cp16(_st + ST_BLO + dstB + _l * (64 * ROWB),                     \
                 g_Blo + srcB + (size_t)_l * 64 * HS + _k0);                 \
        }                                                                    \
        cp_commit();                                                         \
    } while (0)

    // ---- prologue: issue chunks 0,1 ----
    ISSUE_CHUNK(sb + 0 * BUFSZ, 0 * CK);
    ISSUE_CHUNK(sb + 1 * BUFSZ, 1 * CK);

    int stg = 0;
    #pragma unroll 1
    for (int kk = 0; kk < KCH; kk++) {
        if (kk == KCH - 1) cp_wait<0>(); else cp_wait<1>();
        __syncthreads();

        // issue chunk kk+2 into stage (stg+2)%3 (the kk-1 buffer, drained)
        if (kk + 2 < KCH) {
            ISSUE_CHUNK(sb + ((stg + 2) % NSTAGE) * BUFSZ, (kk + 2) * CK);
        }

        const uint32_t bufb = sb + stg * BUFSZ;
        const uint32_t Ahi = bufb + ST_AHI;
        const uint32_t Alo = bufb + ST_ALO;
        const uint32_t Bhi = bufb + ST_BHI;
        const uint32_t Blo = bufb + ST_BLO;

        #pragma unroll
        for (int s = 0; s < 2; s++) {
            const uint32_t ks = s * 32;    // 16 k-elems per step
            uint32_t ah[4][4], al[4][4];
            #pragma unroll
            for (int i = 0; i < 4; i++) {
                uint32_t ra = a_row0 + i * 16 * ROWB + ks;
                ldsm4(ah[i][0], ah[i][1], ah[i][2], ah[i][3], Ahi + ra);
                ldsm4(al[i][0], al[i][1], al[i][2], al[i][3], Alo + ra);
            }
            uint32_t bb[4][4];
            #pragma unroll
            for (int jp = 0; jp < 4; jp++) {
                uint32_t rbo = b_pair0 + jp * 16 * ROWB + ks;
                ldsm4(bb[jp][0], bb[jp][1], bb[jp][2], bb[jp][3], Bhi + rbo);
            }
            // pass 1: Ahi * Bhi
            #pragma unroll
            for (int jp = 0; jp < 4; jp++)
                #pragma unroll
                for (int i = 0; i < 4; i++) {
                    mma_bf16(acc[i][2 * jp],     ah[i], &bb[jp][0]);
                    mma_bf16(acc[i][2 * jp + 1], ah[i], &bb[jp][2]);
                }
            // pass 2: Alo * Bhi
            #pragma unroll
            for (int jp = 0; jp < 4; jp++)
                #pragma unroll
                for (int i = 0; i < 4; i++) {
                    mma_bf16(acc[i][2 * jp],     al[i], &bb[jp][0]);
                    mma_bf16(acc[i][2 * jp + 1], al[i], &bb[jp][2]);
                }
            // reload B registers with Blo
            #pragma unroll
            for (int jp = 0; jp < 4; jp++) {
                uint32_t rbo = b_pair0 + jp * 16 * ROWB + ks;
                ldsm4(bb[jp][0], bb[jp][1], bb[jp][2], bb[jp][3], Blo + rbo);
            }
            // pass 3: Ahi * Blo
            #pragma unroll
            for (int jp = 0; jp < 4; jp++)
                #pragma unroll
                for (int i = 0; i < 4; i++) {
                    mma_bf16(acc[i][2 * jp],     ah[i], &bb[jp][0]);
                    mma_bf16(acc[i][2 * jp + 1], ah[i], &bb[jp][2]);
                }
        }
        stg = (stg + 1) % NSTAGE;
    }

    // -------------------- epilogue: tanh + v-dot --------------------
    float pr[8];
    #pragma unroll
    for (int q = 0; q < 8; q++) pr[q] = 0.f;
    #pragma unroll
    for (int j = 0; j < 8; j++) {
        int col = a0 + warp_n * 64 + j * 8 + (lane & 3) * 2;
        float2 v2 = *reinterpret_cast<const float2*>(v + col);
        float2 d2 = *reinterpret_cast<const float2*>(g_decb + n * HS + col);
        #pragma unroll
        for (int i = 0; i < 4; i++) {
            pr[i * 2 + 0] += v2.x * fast_tanh(acc[i][j][0] + d2.x)
                           + v2.y * fast_tanh(acc[i][j][1] + d2.y);
            pr[i * 2 + 1] += v2.x * fast_tanh(acc[i][j][2] + d2.x)
                           + v2.y * fast_tanh(acc[i][j][3] + d2.y);
        }
    }
    #pragma unroll
    for (int q = 0; q < 8; q++) {
        pr[q] += __shfl_xor_sync(0xffffffffu, pr[q], 1);
        pr[q] += __shfl_xor_sync(0xffffffffu, pr[q], 2);
    }
    float* red = reinterpret_cast<float*>(smem);   // reuse: [128][4]
    __syncthreads();
    if ((lane & 3) == 0) {
        #pragma unroll
        for (int q = 0; q < 8; q++) {
            int row = warp_m * 64 + (q >> 1) * 16 + (lane >> 2) + (q & 1) * 8;
            red[row * 4 + warp_n] = pr[q];
        }
    }
    __syncthreads();
    if (tid < 128) {
        float s = red[tid * 4 + 0] + red[tid * 4 + 1]
                + red[tid * 4 + 2] + red[tid * 4 + 3];
        g_part[(size_t)bn * NROWS + gr0 + tid] = s;
    }
}

// -------------------- masked softmax --------------------
__global__ void softmax_kernel(const int* __restrict__ src_lens,
                               float* __restrict__ weights_out) {
    const int n = blockIdx.x;
    const int tid = threadIdx.x;
    const int len = src_lens[n];
    __shared__ float red[256];

    float sc[8];
    float mx = -1e30f;
    #pragma unroll
    for (int i = 0; i < 8; i++) {
        int t = i * 256 + tid;
        float s = 0.f;
        #pragma unroll
        for (int p = 0; p < NSLICE; p++)
            s += g_part[(size_t)p * NROWS + (size_t)n * TT + t];
        s = (t < len) ? s : -1e10f;
        sc[i] = s;
        mx = fmaxf(mx, s);
    }
    red[tid] = mx; __syncthreads();
    for (int s = 128; s > 0; s >>= 1) {
        if (tid < s) red[tid] = fmaxf(red[tid], red[tid + s]);
        __syncthreads();
    }
    mx = red[0]; __syncthreads();

    float sum = 0.f;
    #pragma unroll
    for (int i = 0; i < 8; i++) { sc[i] = __expf(sc[i] - mx); sum += sc[i]; }
    red[tid] = sum; __syncthreads();
    for (int s = 128; s > 0; s >>= 1) {
        if (tid < s) red[tid] += red[tid + s];
        __syncthreads();
    }
    float inv = __fdividef(1.0f, red[0]);
    #pragma unroll
    for (int i = 0; i < 8; i++) {
        int t = i * 256 + tid;
        weights_out[(size_t)n * TT + t] = sc[i] * inv;
    }
}

// -------------------- ctx (32-way T split + reduce) --------------------
__global__ void ctx_part_kernel(const float* __restrict__ h_enc,
                                const float* __restrict__ weights,
                                const int* __restrict__ src_lens) {
    const int n = blockIdx.x;
    const int ts = blockIdx.z;
    const int t0 = ts * CTX_TCH;
    const int len = src_lens[n];
    if (t0 >= len) return;           // weights exactly 0 there; slot stays 0
    const int tcount = min(CTX_TCH, len - t0);   // trim masked tail
    const int e = blockIdx.y * 256 + threadIdx.x;
    const float* base = h_enc + ((size_t)n * TT + t0) * HS + e;
    const float* wrow = weights + (size_t)n * TT + t0;
    float acc = 0.f;
    #pragma unroll 8
    for (int t = 0; t < tcount; t++)
        acc = fmaf(wrow[t], base[(size_t)t * HS], acc);
    g_ctxp[((size_t)ts * NB + n) * HS + e] = acc;
}

__global__ void ctx_reduce_kernel(float* __restrict__ ctx_out) {
    int i = blockIdx.x * 256 + threadIdx.x;
    float s = 0.f;
    #pragma unroll
    for (int ts = 0; ts < CTX_SPLIT; ts++)
        s += g_ctxp[(size_t)ts * (NB * HS) + i];
    ctx_out[i] = s;
}

// -------------------- launch --------------------
extern "C" void kernel_launch(void* const* d_in, const int* in_sizes, int n_in,
                              void* d_out, int out_size) {
    const float* h_dec    = (const float*)d_in[0];
    const float* h_enc    = (const float*)d_in[1];
    const int*   src_lens = (const int*)  d_in[2];
    const float* W        = (const float*)d_in[3];
    const float* b        = (const float*)d_in[4];
    const float* v        = (const float*)d_in[5];

    float* ctx_out     = (float*)d_out;
    float* weights_out = (float*)d_out + NB * HS;

    // one-time setup (outside capture: first call is the correctness run)
    static cudaStream_t s2 = nullptr;
    static cudaEvent_t evFork = nullptr, evJoin = nullptr;
    if (!s2) {
        cudaFuncSetAttribute(gemm_score_kernel,
                             cudaFuncAttributeMaxDynamicSharedMemorySize, SM_TOT);
        cudaStreamCreateWithFlags(&s2, cudaStreamNonBlocking);
        cudaEventCreateWithFlags(&evFork, cudaEventDisableTiming);
        cudaEventCreateWithFlags(&evJoin, cudaEventDisableTiming);
    }

    // fork: convW + decproj on s2, convA on main stream (all independent)
    cudaEventRecord(evFork, 0);
    cudaStreamWaitEvent(s2, evFork, 0);
    convW_kernel<<<1024, 256, 0, s2>>>(W);
    decproj_kernel<<<dim3(HS / 8, NB), 256, 0, s2>>>(h_dec, W, b);
    cudaEventRecord(evJoin, s2);

    convA_kernel<<<dim3(32, NB), 256>>>(h_enc, src_lens);

    // join before gemm (needs g_Bhi/g_Blo/g_decb and g_Ahi/g_Alo)
    cudaStreamWaitEvent(0, evJoin, 0);

    gemm_score_kernel<<<dim3(NSLICE, NROWS / CM), 256, SM_TOT>>>(v, src_lens);
    softmax_kernel<<<NB, 256>>>(src_lens, weights_out);
    ctx_part_kernel<<<dim3(NB, HS / 256, CTX_SPLIT), 256>>>(h_enc, weights_out, src_lens);
    ctx_reduce_kernel<<<128, 256>>>(ctx_out);
}

// round 17
// speedup vs baseline: 1.1620x; 1.0036x over previous
#include <cuda_runtime.h>
#include <cuda_bf16.h>
#include <cstdint>

// -------------------- problem constants --------------------
#define NB 32
#define TT 2048
#define HS 1024
#define WROW 2048
#define NROWS (NB*TT)      // 65536

// -------------------- GEMM tiling --------------------------
#define CM 128             // CTA rows
#define CN 256             // CTA cols (a)
#define CK 32              // K chunk (bf16 elems) = 64B rows
#define KCH (HS/CK)        // 32 chunks
#define NSLICE (HS/CN)     // 4 partial score slices

// SMEM geometry: 64B rows + 16B pad = 80B stride (conflict-free for ldsm)
#define ROWB 80
#define TILE_A (CM*ROWB)   // 10240 B
#define TILE_B (CN*ROWB)   // 20480 B
#define BUFSZ (2*TILE_A + 2*TILE_B)  // 61440 B per stage
#define NSTAGE 3
#define SM_TOT (NSTAGE*BUFSZ)        // 184320 B -> 1 CTA/SM (256 thr)

#define CTX_SPLIT 32
#define CTX_TCH (TT/CTX_SPLIT)  // 64

// -------------------- device scratch (static, zero-initialized) ----
__device__ __nv_bfloat16 g_Ahi[(size_t)NROWS * HS];   // 128 MB
__device__ __nv_bfloat16 g_Alo[(size_t)NROWS * HS];   // 128 MB
__device__ __nv_bfloat16 g_Bhi[(size_t)HS * HS];      // We hi (2 MB)
__device__ __nv_bfloat16 g_Blo[(size_t)HS * HS];      // We lo
__device__ float g_decb[NB * HS];
__device__ float g_part[(size_t)NSLICE * NROWS];      // 1 MB
__device__ float g_ctxp[CTX_SPLIT * NB * HS];         // 4 MB

// -------------------- small helpers -------------------------
__device__ __forceinline__ uint32_t smem_u32(const void* p) {
    uint32_t a;
    asm("{ .reg .u64 t; cvta.to.shared.u64 t, %1; cvt.u32.u64 %0, t; }"
        : "=r"(a) : "l"(p));
    return a;
}

__device__ __forceinline__ void cp16(uint32_t dst, const void* src) {
    asm volatile("cp.async.cg.shared.global [%0], [%1], 16;"
                 :: "r"(dst), "l"(src));
}
__device__ __forceinline__ void cp_commit() {
    asm volatile("cp.async.commit_group;");
}
template <int N>
__device__ __forceinline__ void cp_wait() {
    asm volatile("cp.async.wait_group %0;" :: "n"(N));
}

__device__ __forceinline__ void ldsm4(uint32_t& r0, uint32_t& r1,
                                      uint32_t& r2, uint32_t& r3, uint32_t a) {
    asm volatile("ldmatrix.sync.aligned.m8n8.x4.shared.b16 {%0,%1,%2,%3}, [%4];"
                 : "=r"(r0), "=r"(r1), "=r"(r2), "=r"(r3) : "r"(a));
}

__device__ __forceinline__ void mma_bf16(float* c, const uint32_t* a,
                                         const uint32_t* b) {
    asm volatile(
        "mma.sync.aligned.m16n8k16.row.col.f32.bf16.bf16.f32 "
        "{%0,%1,%2,%3}, {%4,%5,%6,%7}, {%8,%9}, {%0,%1,%2,%3};"
        : "+f"(c[0]), "+f"(c[1]), "+f"(c[2]), "+f"(c[3])
        : "r"(a[0]), "r"(a[1]), "r"(a[2]), "r"(a[3]), "r"(b[0]), "r"(b[1]));
}

__device__ __forceinline__ float fast_tanh(float x) {
    float e = __expf(2.0f * x);
    return 1.0f - __fdividef(2.0f, e + 1.0f);
}

__device__ __forceinline__ void split_bf16(float x, unsigned short& h, unsigned short& l) {
    __nv_bfloat16 bh = __float2bfloat16(x);
    float r = x - __bfloat162float(bh);
    __nv_bfloat16 bl = __float2bfloat16(r);
    h = __bfloat16_as_ushort(bh);
    l = __bfloat16_as_ushort(bl);
}

// -------------------- conversion kernels --------------------
// grid (32, 32): x = t-block of 64 rows, y = n. Skips fully-masked blocks.
__global__ void convA_kernel(const float* __restrict__ x,
                             const int* __restrict__ src_lens) {
    const int n = blockIdx.y;
    const int tb = blockIdx.x;
    if (tb * 64 >= src_lens[n]) return;      // fully masked: skip (zeros stay)
    const size_t base = ((size_t)n * TT + (size_t)tb * 64) * HS;
    const int tid = threadIdx.x;
    #pragma unroll 4
    for (int it = 0; it < 64; it++) {
        size_t i = base + ((size_t)it * 256 + tid) * 4;
        float4 v = *reinterpret_cast<const float4*>(x + i);
        unsigned short h0, h1, h2, h3, l0, l1, l2, l3;
        split_bf16(v.x, h0, l0); split_bf16(v.y, h1, l1);
        split_bf16(v.z, h2, l2); split_bf16(v.w, h3, l3);
        uint2 hp, lp;
        hp.x = (uint32_t)h0 | ((uint32_t)h1 << 16);
        hp.y = (uint32_t)h2 | ((uint32_t)h3 << 16);
        lp.x = (uint32_t)l0 | ((uint32_t)l1 << 16);
        lp.y = (uint32_t)l2 | ((uint32_t)l3 << 16);
        *reinterpret_cast<uint2*>(&g_Ahi[i]) = hp;
        *reinterpret_cast<uint2*>(&g_Alo[i]) = lp;
    }
}

__global__ void convW_kernel(const float* __restrict__ W) {
    int a = blockIdx.x;
    int e4 = threadIdx.x * 4;
    float4 v = *reinterpret_cast<const float4*>(W + (size_t)a * WROW + HS + e4);
    unsigned short h0, h1, h2, h3, l0, l1, l2, l3;
    split_bf16(v.x, h0, l0); split_bf16(v.y, h1, l1);
    split_bf16(v.z, h2, l2); split_bf16(v.w, h3, l3);
    uint2 hp, lp;
    hp.x = (uint32_t)h0 | ((uint32_t)h1 << 16);
    hp.y = (uint32_t)h2 | ((uint32_t)h3 << 16);
    lp.x = (uint32_t)l0 | ((uint32_t)l1 << 16);
    lp.y = (uint32_t)l2 | ((uint32_t)l3 << 16);
    size_t o = (size_t)a * HS + e4;
    *reinterpret_cast<uint2*>(&g_Bhi[o]) = hp;
    *reinterpret_cast<uint2*>(&g_Blo[o]) = lp;
}

// -------------------- dec_proj + b --------------------
__global__ void decproj_kernel(const float* __restrict__ h_dec,
                               const float* __restrict__ W,
                               const float* __restrict__ b) {
    int warp = threadIdx.x >> 5;
    int lane = threadIdx.x & 31;
    int a = blockIdx.x * 8 + warp;
    int n = blockIdx.y;
    const float* wrow = W + (size_t)a * WROW;
    const float* hd = h_dec + n * HS;
    float s = 0.f;
    #pragma unroll 8
    for (int d = lane; d < HS; d += 32) s += hd[d] * wrow[d];
    #pragma unroll
    for (int off = 16; off > 0; off >>= 1) s += __shfl_xor_sync(0xffffffffu, s, off);
    if (lane == 0) g_decb[n * HS + a] = s + b[a];
}

// -------------------- main GEMM + score kernel (unchanged) --------------
__global__ void __launch_bounds__(256, 1)
gemm_score_kernel(const float* __restrict__ v,
                  const int* __restrict__ src_lens) {
    extern __shared__ char smem[];
    const uint32_t sb = smem_u32(smem);

    const int tid = threadIdx.x;
    const int lane = tid & 31;
    const int wid = tid >> 5;
    const int warp_m = wid & 1;        // 0..1 (64-row slices of 128)
    const int warp_n = wid >> 1;       // 0..3 (64-col slices of 256)

    const int bn = blockIdx.x;         // col block 0..3
    const int rb = blockIdx.y;         // row block 0..511
    const size_t gr0 = (size_t)rb * CM;
    const int a0 = bn * CN;
    const int n = rb >> 4;             // 16 row blocks per batch
    const int t0 = (rb & 15) * CM;     // first timestep of this block

    if (t0 >= src_lens[n]) return;     // all rows masked -> weight 0 anyway

    // ---- global load mapping (256 threads) ----
    const int ld_row = tid >> 2;       // 0..63
    const int ld_u = tid & 3;          // 16B unit
    const size_t srcA0 = (gr0 + ld_row) * (size_t)HS + ld_u * 8;
    const size_t srcA1 = (gr0 + 64 + ld_row) * (size_t)HS + ld_u * 8;
    const uint32_t dstA0 = ld_row * ROWB + ld_u * 16;
    const uint32_t dstA1 = (64 + ld_row) * ROWB + ld_u * 16;
    const size_t srcB = ((size_t)(a0 + ld_row)) * HS + ld_u * 8;
    const uint32_t dstB = ld_row * ROWB + ld_u * 16;

    float acc[4][8][4];
    #pragma unroll
    for (int i = 0; i < 4; i++)
        #pragma unroll
        for (int j = 0; j < 8; j++)
            #pragma unroll
            for (int r = 0; r < 4; r++) acc[i][j][r] = 0.f;

    // ---- ldmatrix per-thread address offsets ----
    const int m_sel = lane >> 3;
    const int m_off = ((m_sel & 1) << 3) + (lane & 7);
    const uint32_t a_kb = (m_sel >> 1) * 16;
    const uint32_t a_row0 = (warp_m * 64 + m_off) * ROWB + a_kb;
    const uint32_t b_pair0 =
        (warp_n * 64 + (lane & 7) + ((lane >> 4) << 3)) * ROWB
        + ((lane >> 3) & 1) * 16;

    #define ST_AHI 0
    #define ST_ALO TILE_A
    #define ST_BHI (2*TILE_A)
    #define ST_BLO (2*TILE_A + TILE_B)

    #define ISSUE_CHUNK(stbase, k0) do {                                     \
        const uint32_t _st = (stbase);                                       \
        const int _k0 = (k0);                                                \
        cp16(_st + ST_AHI + dstA0, g_Ahi + srcA0 + _k0);                     \
        cp16(_st + ST_AHI + dstA1, g_Ahi + srcA1 + _k0);                     \
        cp16(_st + ST_ALO + dstA0, g_Alo + srcA0 + _k0);                     \
        cp16(_st + ST_ALO + dstA1, g_Alo + srcA1 + _k0);                     \
        _Pragma("unroll")                                                    \
        for (int _l = 0; _l < 4; _l++) {                                     \
            cp16(_st + ST_BHI + dstB + _l * (64 * ROWB),                     \
                 g_Bhi + srcB + (size_t)_l * 64 * HS + _k0);                 \
            cp16(_st + ST_BLO + dstB + _l * (64 * ROWB),                     \
                 g_Blo + srcB + (size_t)_l * 64 * HS + _k0);                 \
        }                                                                    \
        cp_commit();                                                         \
    } while (0)

    // ---- prologue: issue chunks 0,1 ----
    ISSUE_CHUNK(sb + 0 * BUFSZ, 0 * CK);
    ISSUE_CHUNK(sb + 1 * BUFSZ, 1 * CK);

    int stg = 0;
    #pragma unroll 1
    for (int kk = 0; kk < KCH; kk++) {
        if (kk == KCH - 1) cp_wait<0>(); else cp_wait<1>();
        __syncthreads();

        // issue chunk kk+2 into stage (stg+2)%3 (the kk-1 buffer, drained)
        if (kk + 2 < KCH) {
            ISSUE_CHUNK(sb + ((stg + 2) % NSTAGE) * BUFSZ, (kk + 2) * CK);
        }

        const uint32_t bufb = sb + stg * BUFSZ;
        const uint32_t Ahi = bufb + ST_AHI;
        const uint32_t Alo = bufb + ST_ALO;
        const uint32_t Bhi = bufb + ST_BHI;
        const uint32_t Blo = bufb + ST_BLO;

        #pragma unroll
        for (int s = 0; s < 2; s++) {
            const uint32_t ks = s * 32;    // 16 k-elems per step
            uint32_t ah[4][4], al[4][4];
            #pragma unroll
            for (int i = 0; i < 4; i++) {
                uint32_t ra = a_row0 + i * 16 * ROWB + ks;
                ldsm4(ah[i][0], ah[i][1], ah[i][2], ah[i][3], Ahi + ra);
                ldsm4(al[i][0], al[i][1], al[i][2], al[i][3], Alo + ra);
            }
            uint32_t bb[4][4];
            #pragma unroll
            for (int jp = 0; jp < 4; jp++) {
                uint32_t rbo = b_pair0 + jp * 16 * ROWB + ks;
                ldsm4(bb[jp][0], bb[jp][1], bb[jp][2], bb[jp][3], Bhi + rbo);
            }
            // pass 1: Ahi * Bhi
            #pragma unroll
            for (int jp = 0; jp < 4; jp++)
                #pragma unroll
                for (int i = 0; i < 4; i++) {
                    mma_bf16(acc[i][2 * jp],     ah[i], &bb[jp][0]);
                    mma_bf16(acc[i][2 * jp + 1], ah[i], &bb[jp][2]);
                }
            // pass 2: Alo * Bhi
            #pragma unroll
            for (int jp = 0; jp < 4; jp++)
                #pragma unroll
                for (int i = 0; i < 4; i++) {
                    mma_bf16(acc[i][2 * jp],     al[i], &bb[jp][0]);
                    mma_bf16(acc[i][2 * jp + 1], al[i], &bb[jp][2]);
                }
            // reload B registers with Blo
            #pragma unroll
            for (int jp = 0; jp < 4; jp++) {
                uint32_t rbo = b_pair0 + jp * 16 * ROWB + ks;
                ldsm4(bb[jp][0], bb[jp][1], bb[jp][2], bb[jp][3], Blo + rbo);
            }
            // pass 3: Ahi * Blo
            #pragma unroll
            for (int jp = 0; jp < 4; jp++)
                #pragma unroll
                for (int i = 0; i < 4; i++) {
                    mma_bf16(acc[i][2 * jp],     ah[i], &bb[jp][0]);
                    mma_bf16(acc[i][2 * jp + 1], ah[i], &bb[jp][2]);
                }
        }
        stg = (stg + 1) % NSTAGE;
    }

    // -------------------- epilogue: tanh + v-dot --------------------
    float pr[8];
    #pragma unroll
    for (int q = 0; q < 8; q++) pr[q] = 0.f;
    #pragma unroll
    for (int j = 0; j < 8; j++) {
        int col = a0 + warp_n * 64 + j * 8 + (lane & 3) * 2;
        float2 v2 = *reinterpret_cast<const float2*>(v + col);
        float2 d2 = *reinterpret_cast<const float2*>(g_decb + n * HS + col);
        #pragma unroll
        for (int i = 0; i < 4; i++) {
            pr[i * 2 + 0] += v2.x * fast_tanh(acc[i][j][0] + d2.x)
                           + v2.y * fast_tanh(acc[i][j][1] + d2.y);
            pr[i * 2 + 1] += v2.x * fast_tanh(acc[i][j][2] + d2.x)
                           + v2.y * fast_tanh(acc[i][j][3] + d2.y);
        }
    }
    #pragma unroll
    for (int q = 0; q < 8; q++) {
        pr[q] += __shfl_xor_sync(0xffffffffu, pr[q], 1);
        pr[q] += __shfl_xor_sync(0xffffffffu, pr[q], 2);
    }
    float* red = reinterpret_cast<float*>(smem);   // reuse: [128][4]
    __syncthreads();
    if ((lane & 3) == 0) {
        #pragma unroll
        for (int q = 0; q < 8; q++) {
            int row = warp_m * 64 + (q >> 1) * 16 + (lane >> 2) + (q & 1) * 8;
            red[row * 4 + warp_n] = pr[q];
        }
    }
    __syncthreads();
    if (tid < 128) {
        float s = red[tid * 4 + 0] + red[tid * 4 + 1]
                + red[tid * 4 + 2] + red[tid * 4 + 3];
        g_part[(size_t)bn * NROWS + gr0 + tid] = s;
    }
}

// -------------------- masked softmax (warp-shuffle reductions) ----------
__global__ void softmax_kernel(const int* __restrict__ src_lens,
                               float* __restrict__ weights_out) {
    const int n = blockIdx.x;
    const int tid = threadIdx.x;
    const int lane = tid & 31;
    const int warp = tid >> 5;
    const int len = src_lens[n];
    __shared__ float red[8];

    float sc[8];
    float mx = -1e30f;
    #pragma unroll
    for (int i = 0; i < 8; i++) {
        int t = i * 256 + tid;
        float s = 0.f;
        #pragma unroll
        for (int p = 0; p < NSLICE; p++)
            s += g_part[(size_t)p * NROWS + (size_t)n * TT + t];
        s = (t < len) ? s : -1e10f;
        sc[i] = s;
        mx = fmaxf(mx, s);
    }
    // warp max -> 8 partials -> warp 0 combines
    #pragma unroll
    for (int off = 16; off > 0; off >>= 1)
        mx = fmaxf(mx, __shfl_xor_sync(0xffffffffu, mx, off));
    if (lane == 0) red[warp] = mx;
    __syncthreads();
    {
        float m = red[tid & 7];
        #pragma unroll
        for (int off = 4; off > 0; off >>= 1)
            m = fmaxf(m, __shfl_xor_sync(0xffffffffu, m, off));
        mx = m;   // all threads now hold the block max (lanes 0-7 pattern
                  // replicated; shuffle tree over 8 values within each warp)
    }

    float sum = 0.f;
    #pragma unroll
    for (int i = 0; i < 8; i++) { sc[i] = __expf(sc[i] - mx); sum += sc[i]; }
    #pragma unroll
    for (int off = 16; off > 0; off >>= 1)
        sum += __shfl_xor_sync(0xffffffffu, sum, off);
    if (lane == 0) red[warp] = sum;
    __syncthreads();
    {
        float s = red[tid & 7];
        #pragma unroll
        for (int off = 4; off > 0; off >>= 1)
            s += __shfl_xor_sync(0xffffffffu, s, off);
        sum = s;
    }
    float inv = __fdividef(1.0f, sum);

    #pragma unroll
    for (int i = 0; i < 8; i++) {
        int t = i * 256 + tid;
        weights_out[(size_t)n * TT + t] = sc[i] * inv;
    }
}

// -------------------- ctx (32-way T split + reduce) --------------------
__global__ void ctx_part_kernel(const float* __restrict__ h_enc,
                                const float* __restrict__ weights,
                                const int* __restrict__ src_lens) {
    const int n = blockIdx.x;
    const int ts = blockIdx.z;
    const int t0 = ts * CTX_TCH;
    const int len = src_lens[n];
    if (t0 >= len) return;           // weights exactly 0 there; slot stays 0
    const int tcount = min(CTX_TCH, len - t0);   // trim masked tail
    const int e = blockIdx.y * 256 + threadIdx.x;
    const float* base = h_enc + ((size_t)n * TT + t0) * HS + e;
    const float* wrow = weights + (size_t)n * TT + t0;
    float acc = 0.f;
    #pragma unroll 8
    for (int t = 0; t < tcount; t++)
        acc = fmaf(wrow[t], base[(size_t)t * HS], acc);
    g_ctxp[((size_t)ts * NB + n) * HS + e] = acc;
}

__global__ void ctx_reduce_kernel(float* __restrict__ ctx_out) {
    int i = (blockIdx.x * 256 + threadIdx.x) * 2;   // 64 blocks x 256 x 2
    float2 s = make_float2(0.f, 0.f);
    #pragma unroll
    for (int ts = 0; ts < CTX_SPLIT; ts++) {
        float2 p = *reinterpret_cast<const float2*>(
            &g_ctxp[(size_t)ts * (NB * HS) + i]);
        s.x += p.x; s.y += p.y;
    }
    *reinterpret_cast<float2*>(ctx_out + i) = s;
}

// -------------------- launch --------------------
extern "C" void kernel_launch(void* const* d_in, const int* in_sizes, int n_in,
                              void* d_out, int out_size) {
    const float* h_dec    = (const float*)d_in[0];
    const float* h_enc    = (const float*)d_in[1];
    const int*   src_lens = (const int*)  d_in[2];
    const float* W        = (const float*)d_in[3];
    const float* b        = (const float*)d_in[4];
    const float* v        = (const float*)d_in[5];

    float* ctx_out     = (float*)d_out;
    float* weights_out = (float*)d_out + NB * HS;

    // one-time setup (outside capture: first call is the correctness run)
    static cudaStream_t s2 = nullptr;
    static cudaEvent_t evFork = nullptr, evJoin = nullptr;
    if (!s2) {
        cudaFuncSetAttribute(gemm_score_kernel,
                             cudaFuncAttributeMaxDynamicSharedMemorySize, SM_TOT);
        cudaStreamCreateWithFlags(&s2, cudaStreamNonBlocking);
        cudaEventCreateWithFlags(&evFork, cudaEventDisableTiming);
        cudaEventCreateWithFlags(&evJoin, cudaEventDisableTiming);
    }

    // fork: convW + decproj on s2, convA on main stream (all independent)
    cudaEventRecord(evFork, 0);
    cudaStreamWaitEvent(s2, evFork, 0);
    convW_kernel<<<1024, 256, 0, s2>>>(W);
    decproj_kernel<<<dim3(HS / 8, NB), 256, 0, s2>>>(h_dec, W, b);
    cudaEventRecord(evJoin, s2);

    convA_kernel<<<dim3(32, NB), 256>>>(h_enc, src_lens);

    // join before gemm (needs g_Bhi/g_Blo/g_decb and g_Ahi/g_Alo)
    cudaStreamWaitEvent(0, evJoin, 0);

    gemm_score_kernel<<<dim3(NSLICE, NROWS / CM), 256, SM_TOT>>>(v, src_lens);
    softmax_kernel<<<NB, 256>>>(src_lens, weights_out);
    ctx_part_kernel<<<dim3(NB, HS / 256, CTX_SPLIT), 256>>>(h_enc, weights_out, src_lens);
    ctx_reduce_kernel<<<64, 256>>>(ctx_out);
}